// round 3
// baseline (speedup 1.0000x reference)
#include <cuda_runtime.h>

// Problem constants
#define BB 16
#define HH 768
#define WW 1280
#define PAD 4

// out = (dsp*w + eps)/(w + eps) = dsp + eps*(1-dsp)/(w+eps)
// w in [0.1492, 0.1690] always  =>  |out - dsp| <= 6.7e-12 absolute.
// Interior output == estDisp shifted by (+4,+4), except where dsp ~ 0
// (exact zeros DO occur in uniform inputs; guarded by the min-check).

__device__ __forceinline__ float4 ld4(const float* p) {
    return *reinterpret_cast<const float4*>(p);
}

__device__ __forceinline__ float full_formula(const float* imgB, const float* estB,
                                              int y, int xi)
{
    const float dist = 0.16901332f;   // exp(-32/18)
    const float eps  = 1e-12f;
    float dsp = 0.0f;
    if (y >= PAD && xi >= PAD)
        dsp = estB[(y - PAD) * WW + (xi - PAD)];
    float c = imgB[y * WW + xi];
    float s = 0.0f;
    if (y + PAD < HH && xi + PAD < WW)
        s = imgB[(y + PAD) * WW + (xi + PAD)];
    float d = c - s;
    float w = dist * __expf(d * d * (-0.125f));
    return (dsp * w + eps) / (w + eps);
}

__global__ __launch_bounds__(256) void bilateral_kernel(
    const float* __restrict__ img,
    const float* __restrict__ est,
    float* __restrict__ out)
{
    // Each thread handles 16 consecutive x (four float4s). 1280/16 = 80 chunks/row.
    const int CPR = WW / 16;  // 80
    const int tid = blockIdx.x * blockDim.x + threadIdx.x;
    const int total = BB * HH * CPR;
    if (tid >= total) return;

    const int xc = tid % CPR;
    const int yb = tid / CPR;
    const int y  = yb % HH;
    const int b  = yb / HH;
    const int x  = xc * 16;

    const float* imgB = img + b * (HH * WW);
    const float* estB = est + b * (HH * WW);
    float*       outB = out + b * (HH * WW);

    if (y >= PAD && x >= PAD) {
        // est addresses x-4 .. x+11 : four aligned float4 loads, front-batched
        const float* src = estB + (y - PAD) * WW + (x - PAD);
        float4 d0 = ld4(src);
        float4 d1 = ld4(src + 4);
        float4 d2 = ld4(src + 8);
        float4 d3 = ld4(src + 12);

        float m0 = fminf(fminf(d0.x, d0.y), fminf(d0.z, d0.w));
        float m1 = fminf(fminf(d1.x, d1.y), fminf(d1.z, d1.w));
        float m2 = fminf(fminf(d2.x, d2.y), fminf(d2.z, d2.w));
        float m3 = fminf(fminf(d3.x, d3.y), fminf(d3.z, d3.w));
        float mn = fminf(fminf(m0, m1), fminf(m2, m3));

        if (mn >= 1e-5f) {
            float4* dst = reinterpret_cast<float4*>(outB + y * WW + x);
            dst[0] = d0;
            dst[1] = d1;
            dst[2] = d2;
            dst[3] = d3;
            return;
        }
        // fall through to exact path (rare: some dsp < 1e-5)
    }

    // Exact path: boundary chunks (x==0 or y<4) and rare tiny-dsp chunks.
    float r[16];
#pragma unroll
    for (int i = 0; i < 16; i++)
        r[i] = full_formula(imgB, estB, y, x + i);

    float4* dst = reinterpret_cast<float4*>(outB + y * WW + x);
#pragma unroll
    for (int v = 0; v < 4; v++)
        dst[v] = make_float4(r[4*v], r[4*v+1], r[4*v+2], r[4*v+3]);
}

extern "C" void kernel_launch(void* const* d_in, const int* in_sizes, int n_in,
                              void* d_out, int out_size)
{
    const float* img = (const float*)d_in[0];   // leftImage
    const float* est = (const float*)d_in[1];   // estDisp
    float* out = (float*)d_out;

    const int total = BB * HH * (WW / 16);      // 983,040 threads
    const int threads = 256;
    const int blocks = (total + threads - 1) / threads;   // 3840
    bilateral_kernel<<<blocks, threads>>>(img, est, out);
}

// round 4
// speedup vs baseline: 1.2277x; 1.2277x over previous
#include <cuda_runtime.h>

// Problem constants
#define BB 16
#define HH 768
#define WW 1280
#define PAD 4
#define IMG  (HH * WW)        // 983,040 floats per image
#define IMG4 (HH * (WW/4))    // 245,760 float4-chunks per image

// out = (dsp*w + eps)/(w + eps) = dsp + eps*(1-dsp)/(w+eps)
// w in [0.1492, 0.1690] always  =>  |out - dsp| <= 6.7e-12 absolute.
// Interior output == estDisp shifted by (+4,+4) except where dsp ~ 0
// (exact zeros occur in uniform inputs; guarded by the min-check, which
// falls back to the exact formula).

__device__ __forceinline__ float4 ld4(const float* p) {
    return *reinterpret_cast<const float4*>(p);
}

__device__ __forceinline__ float full_formula(const float* imgB, const float* estB,
                                              int y, int xi)
{
    const float dist = 0.16901332f;   // exp(-32/18)
    const float eps  = 1e-12f;
    float dsp = 0.0f;
    if (y >= PAD && xi >= PAD)
        dsp = estB[(y - PAD) * WW + (xi - PAD)];
    float c = imgB[y * WW + xi];
    float s = 0.0f;
    if (y + PAD < HH && xi + PAD < WW)
        s = imgB[(y + PAD) * WW + (xi + PAD)];
    float d = c - s;
    float w = dist * __expf(d * d * (-0.125f));
    return (dsp * w + eps) / (w + eps);
}

__device__ __forceinline__ void slow_chunk(const float* img, const float* est,
                                           float* out, int b, int y, int x)
{
    const float* imgB = img + b * IMG;
    const float* estB = est + b * IMG;
    float r[4];
#pragma unroll
    for (int i = 0; i < 4; i++)
        r[i] = full_formula(imgB, estB, y, x + i);
    *reinterpret_cast<float4*>(out + b * IMG + y * WW + x) =
        make_float4(r[0], r[1], r[2], r[3]);
}

__device__ __forceinline__ void emit(const float* img, const float* est,
                                     float* out, int b, int y, int x, float4 d)
{
    float mn = fminf(fminf(d.x, d.y), fminf(d.z, d.w));
    if (mn >= 1e-5f) {
        *reinterpret_cast<float4*>(out + b * IMG + y * WW + x) = d;
    } else {
        slow_chunk(img, est, out, b, y, x);   // rare: some dsp < 1e-5
    }
}

__global__ __launch_bounds__(256) void bilateral_kernel(
    const float* __restrict__ img,
    const float* __restrict__ est,
    float* __restrict__ out)
{
    // Each thread: one float4 location, replicated across 4 batch images
    // (b, b+4, b+8, b+12) -> 4 independent, perfectly coalesced loads.
    const int tid = blockIdx.x * blockDim.x + threadIdx.x;
    const int nthreads = 4 * IMG4;               // 983,040
    if (tid >= nthreads) return;

    const int b0  = tid / IMG4;                  // 0..3
    const int rem = tid % IMG4;
    const int y   = rem / (WW / 4);
    const int x   = (rem % (WW / 4)) * 4;

    if (y >= PAD && x >= PAD) {
        const float* src = est + (y - PAD) * WW + (x - PAD);
        // front-batched independent loads (MLP = 4)
        float4 d0 = ld4(src + (b0     ) * IMG);
        float4 d1 = ld4(src + (b0 +  4) * IMG);
        float4 d2 = ld4(src + (b0 +  8) * IMG);
        float4 d3 = ld4(src + (b0 + 12) * IMG);

        emit(img, est, out, b0,      y, x, d0);
        emit(img, est, out, b0 +  4, y, x, d1);
        emit(img, est, out, b0 +  8, y, x, d2);
        emit(img, est, out, b0 + 12, y, x, d3);
    } else {
        // boundary rows/cols: exact formula for all four batches
        slow_chunk(img, est, out, b0,      y, x);
        slow_chunk(img, est, out, b0 +  4, y, x);
        slow_chunk(img, est, out, b0 +  8, y, x);
        slow_chunk(img, est, out, b0 + 12, y, x);
    }
}

extern "C" void kernel_launch(void* const* d_in, const int* in_sizes, int n_in,
                              void* d_out, int out_size)
{
    const float* img = (const float*)d_in[0];   // leftImage
    const float* est = (const float*)d_in[1];   // estDisp
    float* out = (float*)d_out;

    const int nthreads = 4 * IMG4;              // 983,040
    const int threads = 256;
    const int blocks = (nthreads + threads - 1) / threads;   // 3840
    bilateral_kernel<<<blocks, threads>>>(img, est, out);
}

// round 6
// speedup vs baseline: 1.3906x; 1.1327x over previous
#include <cuda_runtime.h>

// Problem constants
#define BB 16
#define HH 768
#define WW 1280
#define PAD 4

// out = (dsp*w + eps)/(w + eps) = dsp + eps*(1-dsp)/(w+eps)
// w in [0.1492, 0.1690] always  =>  |out - dsp| <= 6.7e-12 absolute.
// Interior output == estDisp shifted by (+4,+4), except where dsp ~ 0
// (exact zeros occur in uniform inputs; guarded by the min-check).
//
// Cache policy (steady-state graph replay): out (63MB) is write-only ->
// stream it with st.global.cs (evict-first) so it doesn't evict est (63MB)
// from the ~126MB L2. est then re-hits L2 on every replay; DRAM traffic
// drops to ~the output writeback stream.

__device__ __forceinline__ float4 ld4(const float* p) {
    return __ldg(reinterpret_cast<const float4*>(p));
}

__device__ __forceinline__ void st4_cs(float* p, float4 v) {
    __stcs(reinterpret_cast<float4*>(p), v);
}

__device__ __forceinline__ float full_formula(const float* imgB, const float* estB,
                                              int y, int xi)
{
    const float dist = 0.16901332f;   // exp(-32/18)
    const float eps  = 1e-12f;
    float dsp = 0.0f;
    if (y >= PAD && xi >= PAD)
        dsp = estB[(y - PAD) * WW + (xi - PAD)];
    float c = imgB[y * WW + xi];
    float s = 0.0f;
    if (y + PAD < HH && xi + PAD < WW)
        s = imgB[(y + PAD) * WW + (xi + PAD)];
    float d = c - s;
    float w = dist * __expf(d * d * (-0.125f));
    return (dsp * w + eps) / (w + eps);
}

__global__ __launch_bounds__(256) void bilateral_kernel(
    const float* __restrict__ img,
    const float* __restrict__ est,
    float* __restrict__ out)
{
    // Each thread handles 8 consecutive x (two float4s). 1280/8 = 160 chunks/row.
    const int CPR = WW / 8;   // 160
    const int tid = blockIdx.x * blockDim.x + threadIdx.x;
    const int total = BB * HH * CPR;
    if (tid >= total) return;

    const int x8 = tid % CPR;
    const int yb = tid / CPR;
    const int y  = yb % HH;
    const int b  = yb / HH;
    const int x  = x8 * 8;

    const float* imgB = img + (long long)b * HH * WW;
    const float* estB = est + (long long)b * HH * WW;
    float*       outB = out + (long long)b * HH * WW;

    if (y >= PAD && x >= PAD) {
        // est addresses x-4 .. x+3 : two aligned float4 loads (x multiple of 8)
        const float* src = estB + (y - PAD) * WW + (x - PAD);
        float4 d0 = ld4(src);
        float4 d1 = ld4(src + 4);

        float mn = fminf(fminf(fminf(d0.x, d0.y), fminf(d0.z, d0.w)),
                         fminf(fminf(d1.x, d1.y), fminf(d1.z, d1.w)));
        if (mn >= 1e-5f) {
            float* dst = outB + y * WW + x;
            st4_cs(dst,     d0);
            st4_cs(dst + 4, d1);
            return;
        }
        // fall through to exact path (rare: some dsp < 1e-5)
    }

    // Exact path: boundary chunks (x==0 or y<4) and rare tiny-dsp chunks.
    float r[8];
#pragma unroll
    for (int i = 0; i < 8; i++)
        r[i] = full_formula(imgB, estB, y, x + i);

    float* dst = outB + y * WW + x;
    st4_cs(dst,     make_float4(r[0], r[1], r[2], r[3]));
    st4_cs(dst + 4, make_float4(r[4], r[5], r[6], r[7]));
}

extern "C" void kernel_launch(void* const* d_in, const int* in_sizes, int n_in,
                              void* d_out, int out_size)
{
    const float* img = (const float*)d_in[0];   // leftImage
    const float* est = (const float*)d_in[1];   // estDisp
    float* out = (float*)d_out;

    const int total = BB * HH * (WW / 8);       // 1,966,080 threads
    const int threads = 256;
    const int blocks = (total + threads - 1) / threads;   // 7680
    bilateral_kernel<<<blocks, threads>>>(img, est, out);
}